// round 9
// baseline (speedup 1.0000x reference)
#include <cuda_runtime.h>
#include <math.h>

// ---------------- problem constants ----------------
#define N_ROWS   32768      // B*S = 8*4096
#define DIM      256
#define NCODES   8192
#define BETA_F   0.25f
#define ND       (N_ROWS * DIM)   // 8388608

// ---------------- device scratch (no allocs allowed) ----------------
__device__ float g_ee[NCODES];         // ||e_k||^2
__device__ int   g_idx[N_ROWS];        // argmin index per row
__device__ int   g_counts[NCODES];     // usage histogram
__device__ float g_partial[N_ROWS / 8];// per-block loss partial sums (4096)

// ---------------- packed f32x2 helpers (FFMA2 path) ----------------
#define FMA_F32X2(d, a, b, c) \
    asm("fma.rn.f32x2 %0, %1, %2, %3;" : "=l"(d) : "l"(a), "l"(b), "l"(c))

#define PACK_DUP_F32(d, x) \
    asm("mov.b64 %0, {%1, %1};" : "=l"(d) : "r"(__float_as_uint(x)))

#define UNPACK_F32X2(lo, hi, v) \
    asm("mov.b64 {%0, %1}, %2;" : "=r"(lo), "=r"(hi) : "l"(v))

// ---------------- kernel 0: zero the histogram ----------------
__global__ void zero_counts_kernel() {
    int i = blockIdx.x * blockDim.x + threadIdx.x;
    if (i < NCODES) g_counts[i] = 0;
}

// ---------------- kernel 1: ||e_k||^2, one warp per code ----------------
__global__ __launch_bounds__(256) void ee_kernel(const float* __restrict__ embed) {
    int warp = (blockIdx.x * blockDim.x + threadIdx.x) >> 5;
    int lane = threadIdx.x & 31;
    if (warp >= NCODES) return;
    const float4* p = reinterpret_cast<const float4*>(embed + (size_t)warp * DIM);
    float s = 0.f;
    #pragma unroll
    for (int k = 0; k < 2; ++k) {
        float4 v = p[k * 32 + lane];
        s += v.x * v.x + v.y * v.y + v.z * v.z + v.w * v.w;
    }
    #pragma unroll
    for (int off = 16; off > 0; off >>= 1)
        s += __shfl_xor_sync(0xffffffffu, s, off);
    if (lane == 0) g_ee[warp] = s;
}

// ---------------- kernel 2: fused GEMM + argmin ----------------
// 128 rows x 128 codes per tile, 256 threads (16x16), 8x8 per-thread tile,
// D chunked by 16 through shared memory, FFMA2 inner product.
#define BM 128
#define BN 128
#define BD 16
#define SSTR 132   // padded shared stride (bank-conflict free; keeps 16B align)

__global__ __launch_bounds__(256, 2)
void argmin_kernel(const float* __restrict__ z, const float* __restrict__ embed) {
    __shared__ __align__(16) float As[BD][SSTR];
    __shared__ __align__(16) float Bs[BD][SSTR];
    __shared__ float ee_s[BN];
    __shared__ float red_d[BM][17];
    __shared__ int   red_i[BM][17];

    const int tid = threadIdx.x;
    const int tx = tid & 15;          // code-column group 0..15
    const int ty = tid >> 4;          // row group 0..15
    const int rowBase = blockIdx.x * BM;

    // global->shared load mapping: 512 float4 per tile, 2 per thread
    const int v0 = tid * 2, v1 = tid * 2 + 1;
    const int rA0 = v0 >> 2, q0 = (v0 & 3) * 4;
    const int rA1 = v1 >> 2, q1 = (v1 & 3) * 4;

    float best_d[8];
    int   best_i[8];
    #pragma unroll
    for (int i = 0; i < 8; ++i) { best_d[i] = 3.4e38f; best_i[i] = 0; }

    for (int cBase = 0; cBase < NCODES; cBase += BN) {
        unsigned long long acc2[8][4];
        #pragma unroll
        for (int i = 0; i < 8; ++i)
            #pragma unroll
            for (int jj = 0; jj < 4; ++jj) acc2[i][jj] = 0ull;

        for (int dBase = 0; dBase < DIM; dBase += BD) {
            __syncthreads();   // prior tile / ee_s fully consumed
            {
                float4 a = *reinterpret_cast<const float4*>(
                    z + (size_t)(rowBase + rA0) * DIM + dBase + q0);
                As[q0 + 0][rA0] = a.x; As[q0 + 1][rA0] = a.y;
                As[q0 + 2][rA0] = a.z; As[q0 + 3][rA0] = a.w;
                float4 a2 = *reinterpret_cast<const float4*>(
                    z + (size_t)(rowBase + rA1) * DIM + dBase + q1);
                As[q1 + 0][rA1] = a2.x; As[q1 + 1][rA1] = a2.y;
                As[q1 + 2][rA1] = a2.z; As[q1 + 3][rA1] = a2.w;
                float4 b = *reinterpret_cast<const float4*>(
                    embed + (size_t)(cBase + rA0) * DIM + dBase + q0);
                Bs[q0 + 0][rA0] = b.x; Bs[q0 + 1][rA0] = b.y;
                Bs[q0 + 2][rA0] = b.z; Bs[q0 + 3][rA0] = b.w;
                float4 b2 = *reinterpret_cast<const float4*>(
                    embed + (size_t)(cBase + rA1) * DIM + dBase + q1);
                Bs[q1 + 0][rA1] = b2.x; Bs[q1 + 1][rA1] = b2.y;
                Bs[q1 + 2][rA1] = b2.z; Bs[q1 + 3][rA1] = b2.w;
                if (dBase == 0 && tid < BN) ee_s[tid] = g_ee[cBase + tid];
            }
            __syncthreads();

            #pragma unroll
            for (int bd = 0; bd < BD; ++bd) {
                float4 a0 = *reinterpret_cast<const float4*>(&As[bd][ty * 8]);
                float4 a1 = *reinterpret_cast<const float4*>(&As[bd][ty * 8 + 4]);
                ulonglong2 bp0 = *reinterpret_cast<const ulonglong2*>(&Bs[bd][tx * 8]);
                ulonglong2 bp1 = *reinterpret_cast<const ulonglong2*>(&Bs[bd][tx * 8 + 4]);
                float av[8] = {a0.x, a0.y, a0.z, a0.w, a1.x, a1.y, a1.z, a1.w};
                unsigned long long bv[4] = {bp0.x, bp0.y, bp1.x, bp1.y};
                #pragma unroll
                for (int i = 0; i < 8; ++i) {
                    unsigned long long ad;
                    PACK_DUP_F32(ad, av[i]);
                    #pragma unroll
                    for (int jj = 0; jj < 4; ++jj)
                        FMA_F32X2(acc2[i][jj], ad, bv[jj], acc2[i][jj]);
                }
            }
        }

        // epilogue: dist' = ee - 2*dot, running argmin (columns visited in
        // increasing order -> strict < keeps lowest index, matching jnp.argmin)
        #pragma unroll
        for (int i = 0; i < 8; ++i) {
            #pragma unroll
            for (int jj = 0; jj < 4; ++jj) {
                unsigned int u0, u1;
                UNPACK_F32X2(u0, u1, acc2[i][jj]);
                float s0 = __uint_as_float(u0);
                float s1 = __uint_as_float(u1);
                int col = cBase + tx * 8 + jj * 2;
                float d0 = fmaf(-2.f, s0, ee_s[tx * 8 + jj * 2]);
                float d1 = fmaf(-2.f, s1, ee_s[tx * 8 + jj * 2 + 1]);
                if (d0 < best_d[i]) { best_d[i] = d0; best_i[i] = col; }
                if (d1 < best_d[i]) { best_d[i] = d1; best_i[i] = col + 1; }
            }
        }
    }

    // cross-thread reduction over the 16 column groups per row
    __syncthreads();
    #pragma unroll
    for (int i = 0; i < 8; ++i) {
        red_d[ty * 8 + i][tx] = best_d[i];
        red_i[ty * 8 + i][tx] = best_i[i];
    }
    __syncthreads();
    if (tid < BM) {
        float bd = red_d[tid][0];
        int   bi = red_i[tid][0];
        #pragma unroll
        for (int t = 1; t < 16; ++t) {
            float dd = red_d[tid][t];
            int   ii = red_i[tid][t];
            if (dd < bd || (dd == bd && ii < bi)) { bd = dd; bi = ii; }
        }
        g_idx[rowBase + tid] = bi;
    }
}

// ---------------- kernel 3: gather z_q, loss partials, histogram, idx ----
__global__ __launch_bounds__(256)
void gather_kernel(const float* __restrict__ z, const float* __restrict__ embed,
                   float* __restrict__ out, int write_idx) {
    __shared__ float sh[8];
    int w = threadIdx.x >> 5, lane = threadIdx.x & 31;
    int row = blockIdx.x * 8 + w;
    int idx = g_idx[row];
    const float4* pe = reinterpret_cast<const float4*>(embed + (size_t)idx * DIM);
    const float4* pz = reinterpret_cast<const float4*>(z + (size_t)row * DIM);
    float4*       po = reinterpret_cast<float4*>(out + (size_t)row * DIM);
    float s = 0.f;
    #pragma unroll
    for (int k = 0; k < 2; ++k) {
        float4 e  = pe[k * 32 + lane];
        float4 zz = pz[k * 32 + lane];
        po[k * 32 + lane] = e;   // z_q_st value == z_q
        float dx = e.x - zz.x, dy = e.y - zz.y, dz2 = e.z - zz.z, dw = e.w - zz.w;
        s += dx * dx + dy * dy + dz2 * dz2 + dw * dw;
    }
    #pragma unroll
    for (int off = 16; off > 0; off >>= 1)
        s += __shfl_xor_sync(0xffffffffu, s, off);
    if (lane == 0) {
        sh[w] = s;
        atomicAdd(&g_counts[idx], 1);          // int atomics: deterministic
        if (write_idx) out[ND + 2 + row] = (float)idx;
    }
    __syncthreads();
    if (threadIdx.x == 0) {
        float t = 0.f;
        #pragma unroll
        for (int i = 0; i < 8; ++i) t += sh[i];   // fixed order: deterministic
        g_partial[blockIdx.x] = t;
    }
}

// ---------------- kernel 4: loss + perplexity (single block) ----------------
__global__ __launch_bounds__(256)
void finalize_kernel(float* __restrict__ out, int write_scalars) {
    __shared__ float sh[256];
    int tid = threadIdx.x;

    float s = 0.f;
    for (int i = tid; i < N_ROWS / 8; i += 256) s += g_partial[i];
    sh[tid] = s; __syncthreads();
    for (int off = 128; off > 0; off >>= 1) {
        if (tid < off) sh[tid] += sh[tid + off];
        __syncthreads();
    }
    float loss = sh[0] * (BETA_F / (float)ND);
    __syncthreads();

    float ps = 0.f;
    const float invN = 1.f / (float)N_ROWS;
    for (int i = tid; i < NCODES; i += 256) {
        float p = (float)g_counts[i] * invN;
        ps += p * logf(p + 1e-12f);
    }
    sh[tid] = ps; __syncthreads();
    for (int off = 128; off > 0; off >>= 1) {
        if (tid < off) sh[tid] += sh[tid + off];
        __syncthreads();
    }
    if (tid == 0 && write_scalars) {
        out[ND]     = loss;
        out[ND + 1] = expf(-sh[0]);
    }
}

// ---------------- launch ----------------
extern "C" void kernel_launch(void* const* d_in, const int* in_sizes, int n_in,
                              void* d_out, int out_size) {
    const float* z     = (const float*)d_in[0];   // [B,S,D] fp32
    const float* embed = (const float*)d_in[1];   // [K,D]  fp32
    float* out = (float*)d_out;
    (void)in_sizes; (void)n_in;

    int write_scalars = (out_size >= ND + 2) ? 1 : 0;
    int write_idx     = (out_size >= ND + 2 + N_ROWS) ? 1 : 0;

    zero_counts_kernel<<<(NCODES + 255) / 256, 256>>>();
    ee_kernel<<<NCODES / 8, 256>>>(embed);
    argmin_kernel<<<N_ROWS / BM, 256>>>(z, embed);
    gather_kernel<<<N_ROWS / 8, 256>>>(z, embed, out, write_idx);
    finalize_kernel<<<1, 256>>>(out, write_scalars);
}

// round 10
// speedup vs baseline: 1.1508x; 1.1508x over previous
#include <cuda_runtime.h>
#include <math.h>

// ---------------- problem constants ----------------
#define N_ROWS   32768      // B*S = 8*4096
#define DIM      256
#define NCODES   8192
#define BETA_F   0.25f
#define ND       (N_ROWS * DIM)   // 8388608

// ---------------- device scratch (no allocs allowed) ----------------
__device__ float g_ee[NCODES];         // ||e_k||^2
__device__ int   g_idx[N_ROWS];        // argmin index per row
__device__ int   g_counts[NCODES];     // usage histogram
__device__ float g_partial[N_ROWS / 8];// per-block loss partial sums (4096)

// ---------------- packed f32x2 helpers (FFMA2 path) ----------------
#define FMA_F32X2(d, a, b, c) \
    asm("fma.rn.f32x2 %0, %1, %2, %3;" : "=l"(d) : "l"(a), "l"(b), "l"(c))

#define PACK_DUP_F32(d, x) \
    asm("mov.b64 %0, {%1, %1};" : "=l"(d) : "r"(__float_as_uint(x)))

#define UNPACK_F32X2(lo, hi, v) \
    asm("mov.b64 {%0, %1}, %2;" : "=r"(lo), "=r"(hi) : "l"(v))

// ---------------- kernel 0: zero the histogram ----------------
__global__ void zero_counts_kernel() {
    int i = blockIdx.x * blockDim.x + threadIdx.x;
    if (i < NCODES) g_counts[i] = 0;
}

// ---------------- kernel 1: ||e_k||^2, one warp per code ----------------
__global__ __launch_bounds__(256) void ee_kernel(const float* __restrict__ embed) {
    int warp = (blockIdx.x * blockDim.x + threadIdx.x) >> 5;
    int lane = threadIdx.x & 31;
    if (warp >= NCODES) return;
    const float4* p = reinterpret_cast<const float4*>(embed + (size_t)warp * DIM);
    float s = 0.f;
    #pragma unroll
    for (int k = 0; k < 2; ++k) {
        float4 v = p[k * 32 + lane];
        s += v.x * v.x + v.y * v.y + v.z * v.z + v.w * v.w;
    }
    #pragma unroll
    for (int off = 16; off > 0; off >>= 1)
        s += __shfl_xor_sync(0xffffffffu, s, off);
    if (lane == 0) g_ee[warp] = s;
}

// ---------------- kernel 2: fused GEMM + argmin (pipelined v2) ----------------
// 128 rows x 128 codes per tile, 256 threads (16x16), 8x8 per-thread tile.
// Flattened (codeTile, dChunk) loop: 64 x 16 = 1024 chunks of BD=16.
// Register prefetch + double-buffered shared, ONE barrier per chunk.
// Thread column ownership split as {tx*4..tx*4+3, 64+tx*4..64+tx*4+3}
// so both B LDS.128 are bank-conflict-free.
#define BM 128
#define BN 128
#define BD 16
#define SSTR 132                 // padded shared row stride (floats), 16B-aligned rows
#define NUM_CB      (NCODES / BN)        // 64
#define CHUNKS      (NUM_CB * (DIM / BD)) // 1024

__global__ __launch_bounds__(256, 2)
void argmin_kernel(const float* __restrict__ z, const float* __restrict__ embed) {
    __shared__ __align__(16) float As[2][BD][SSTR];
    __shared__ __align__(16) float Bs[2][BD][SSTR];
    __shared__ float ee_s[2][BN];
    __shared__ float red_d[BM][17];
    __shared__ int   red_i[BM][17];

    const int tid = threadIdx.x;
    const int tx  = tid & 15;          // column group 0..15
    const int ty  = tid >> 4;          // row group 0..15
    const int rowBase = blockIdx.x * BM;

    // global->shared mapping: thread loads 2 float4 per tile per chunk,
    // both in row rA at d-offsets q0, q0+4 within the 16-wide chunk.
    const int rA = tid >> 1;
    const int q0 = (tid & 1) * 8;
    const int q1 = q0 + 4;

    // running argmin state lives in shared (epilogue-only access)
    #pragma unroll
    for (int i = 0; i < 8; ++i) {
        red_d[ty * 8 + i][tx] = 3.4e38f;
        red_i[ty * 8 + i][tx] = 0;
    }

    const float* zrow = z + (size_t)(rowBase + rA) * DIM;

    // ---- prologue: load + store chunk 0 (cb=0, db=0) ----
    float4 a_r0, a_r1, b_r0, b_r1;
    float  ee_r = 0.f;
    a_r0 = *reinterpret_cast<const float4*>(zrow + q0);
    a_r1 = *reinterpret_cast<const float4*>(zrow + q1);
    {
        const float* brow = embed + (size_t)rA * DIM;
        b_r0 = *reinterpret_cast<const float4*>(brow + q0);
        b_r1 = *reinterpret_cast<const float4*>(brow + q1);
    }
    if (tid < BN) ee_r = g_ee[tid];

    As[0][q0 + 0][rA] = a_r0.x; As[0][q0 + 1][rA] = a_r0.y;
    As[0][q0 + 2][rA] = a_r0.z; As[0][q0 + 3][rA] = a_r0.w;
    As[0][q1 + 0][rA] = a_r1.x; As[0][q1 + 1][rA] = a_r1.y;
    As[0][q1 + 2][rA] = a_r1.z; As[0][q1 + 3][rA] = a_r1.w;
    Bs[0][q0 + 0][rA] = b_r0.x; Bs[0][q0 + 1][rA] = b_r0.y;
    Bs[0][q0 + 2][rA] = b_r0.z; Bs[0][q0 + 3][rA] = b_r0.w;
    Bs[0][q1 + 0][rA] = b_r1.x; Bs[0][q1 + 1][rA] = b_r1.y;
    Bs[0][q1 + 2][rA] = b_r1.z; Bs[0][q1 + 3][rA] = b_r1.w;
    if (tid < BN) ee_s[0][tid] = ee_r;
    __syncthreads();

    unsigned long long acc2[8][4];

    #pragma unroll 1
    for (int c = 0; c < CHUNKS; ++c) {
        const int buf = c & 1;
        const int cb  = c >> 4;

        // ---- prefetch chunk c+1 into registers (latency hidden by compute) ----
        const int c1  = c + 1;
        const bool have_next = (c1 < CHUNKS);
        if (have_next) {
            const int cb1 = c1 >> 4;
            const int db1 = (c1 & 15) * BD;
            a_r0 = *reinterpret_cast<const float4*>(zrow + db1 + q0);
            a_r1 = *reinterpret_cast<const float4*>(zrow + db1 + q1);
            const float* brow = embed + (size_t)(cb1 * BN + rA) * DIM + db1;
            b_r0 = *reinterpret_cast<const float4*>(brow + q0);
            b_r1 = *reinterpret_cast<const float4*>(brow + q1);
            if (((c1 & 15) == 0) && tid < BN) ee_r = g_ee[cb1 * BN + tid];
        }

        // ---- zero accumulators at the start of each code tile ----
        if ((c & 15) == 0) {
            #pragma unroll
            for (int i = 0; i < 8; ++i)
                #pragma unroll
                for (int jj = 0; jj < 4; ++jj) acc2[i][jj] = 0ull;
        }

        // ---- compute: 16 d-steps of the 8x8 outer product ----
        #pragma unroll
        for (int bd = 0; bd < BD; ++bd) {
            float4 a0 = *reinterpret_cast<const float4*>(&As[buf][bd][ty * 8]);
            float4 a1 = *reinterpret_cast<const float4*>(&As[buf][bd][ty * 8 + 4]);
            ulonglong2 bb0 = *reinterpret_cast<const ulonglong2*>(&Bs[buf][bd][tx * 4]);
            ulonglong2 bb1 = *reinterpret_cast<const ulonglong2*>(&Bs[buf][bd][64 + tx * 4]);
            float av[8] = {a0.x, a0.y, a0.z, a0.w, a1.x, a1.y, a1.z, a1.w};
            unsigned long long bv[4] = {bb0.x, bb0.y, bb1.x, bb1.y};
            #pragma unroll
            for (int i = 0; i < 8; ++i) {
                unsigned long long ad;
                PACK_DUP_F32(ad, av[i]);
                #pragma unroll
                for (int jj = 0; jj < 4; ++jj)
                    FMA_F32X2(acc2[i][jj], ad, bv[jj], acc2[i][jj]);
            }
        }

        // ---- epilogue at end of each code tile: fold into running argmin ----
        // Columns visited in ascending order; strict < keeps the lowest index,
        // matching jnp.argmin tie-breaking.
        if ((c & 15) == 15) {
            const int eb = cb & 1;
            #pragma unroll
            for (int i = 0; i < 8; ++i) {
                const int r = ty * 8 + i;
                float bd_ = red_d[r][tx];
                int   bi_ = red_i[r][tx];
                #pragma unroll
                for (int jj = 0; jj < 4; ++jj) {
                    unsigned int u0, u1;
                    UNPACK_F32X2(u0, u1, acc2[i][jj]);
                    const int eidx = (jj < 2) ? (tx * 4 + jj * 2)
                                              : (64 + tx * 4 + (jj - 2) * 2);
                    const int col  = cb * BN + eidx;
                    float d0 = fmaf(-2.f, __uint_as_float(u0), ee_s[eb][eidx]);
                    float d1 = fmaf(-2.f, __uint_as_float(u1), ee_s[eb][eidx + 1]);
                    if (d0 < bd_) { bd_ = d0; bi_ = col; }
                    if (d1 < bd_) { bd_ = d1; bi_ = col + 1; }
                }
                red_d[r][tx] = bd_;
                red_i[r][tx] = bi_;
            }
        }

        // ---- store prefetched chunk into the other buffer ----
        if (have_next) {
            const int nb = buf ^ 1;
            As[nb][q0 + 0][rA] = a_r0.x; As[nb][q0 + 1][rA] = a_r0.y;
            As[nb][q0 + 2][rA] = a_r0.z; As[nb][q0 + 3][rA] = a_r0.w;
            As[nb][q1 + 0][rA] = a_r1.x; As[nb][q1 + 1][rA] = a_r1.y;
            As[nb][q1 + 2][rA] = a_r1.z; As[nb][q1 + 3][rA] = a_r1.w;
            Bs[nb][q0 + 0][rA] = b_r0.x; Bs[nb][q0 + 1][rA] = b_r0.y;
            Bs[nb][q0 + 2][rA] = b_r0.z; Bs[nb][q0 + 3][rA] = b_r0.w;
            Bs[nb][q1 + 0][rA] = b_r1.x; Bs[nb][q1 + 1][rA] = b_r1.y;
            Bs[nb][q1 + 2][rA] = b_r1.z; Bs[nb][q1 + 3][rA] = b_r1.w;
            if (((c1 & 15) == 0) && tid < BN)
                ee_s[(c1 >> 4) & 1][tid] = ee_r;
        }
        __syncthreads();
    }

    // ---- final cross-thread reduction over the 16 column groups per row ----
    if (tid < BM) {
        float bd = red_d[tid][0];
        int   bi = red_i[tid][0];
        #pragma unroll
        for (int t = 1; t < 16; ++t) {
            float dd = red_d[tid][t];
            int   ii = red_i[tid][t];
            if (dd < bd || (dd == bd && ii < bi)) { bd = dd; bi = ii; }
        }
        g_idx[rowBase + tid] = bi;
    }
}

// ---------------- kernel 3: gather z_q, loss partials, histogram, idx ----
__global__ __launch_bounds__(256)
void gather_kernel(const float* __restrict__ z, const float* __restrict__ embed,
                   float* __restrict__ out, int write_idx) {
    __shared__ float sh[8];
    int w = threadIdx.x >> 5, lane = threadIdx.x & 31;
    int row = blockIdx.x * 8 + w;
    int idx = g_idx[row];
    const float4* pe = reinterpret_cast<const float4*>(embed + (size_t)idx * DIM);
    const float4* pz = reinterpret_cast<const float4*>(z + (size_t)row * DIM);
    float4*       po = reinterpret_cast<float4*>(out + (size_t)row * DIM);
    float s = 0.f;
    #pragma unroll
    for (int k = 0; k < 2; ++k) {
        float4 e  = pe[k * 32 + lane];
        float4 zz = pz[k * 32 + lane];
        po[k * 32 + lane] = e;   // z_q_st value == z_q
        float dx = e.x - zz.x, dy = e.y - zz.y, dz2 = e.z - zz.z, dw = e.w - zz.w;
        s += dx * dx + dy * dy + dz2 * dz2 + dw * dw;
    }
    #pragma unroll
    for (int off = 16; off > 0; off >>= 1)
        s += __shfl_xor_sync(0xffffffffu, s, off);
    if (lane == 0) {
        sh[w] = s;
        atomicAdd(&g_counts[idx], 1);          // int atomics: deterministic
        if (write_idx) out[ND + 2 + row] = (float)idx;
    }
    __syncthreads();
    if (threadIdx.x == 0) {
        float t = 0.f;
        #pragma unroll
        for (int i = 0; i < 8; ++i) t += sh[i];   // fixed order: deterministic
        g_partial[blockIdx.x] = t;
    }
}

// ---------------- kernel 4: loss + perplexity (single block) ----------------
__global__ __launch_bounds__(256)
void finalize_kernel(float* __restrict__ out, int write_scalars) {
    __shared__ float sh[256];
    int tid = threadIdx.x;

    float s = 0.f;
    for (int i = tid; i < N_ROWS / 8; i += 256) s += g_partial[i];
    sh[tid] = s; __syncthreads();
    for (int off = 128; off > 0; off >>= 1) {
        if (tid < off) sh[tid] += sh[tid + off];
        __syncthreads();
    }
    float loss = sh[0] * (BETA_F / (float)ND);
    __syncthreads();

    float ps = 0.f;
    const float invN = 1.f / (float)N_ROWS;
    for (int i = tid; i < NCODES; i += 256) {
        float p = (float)g_counts[i] * invN;
        ps += p * logf(p + 1e-12f);
    }
    sh[tid] = ps; __syncthreads();
    for (int off = 128; off > 0; off >>= 1) {
        if (tid < off) sh[tid] += sh[tid + off];
        __syncthreads();
    }
    if (tid == 0 && write_scalars) {
        out[ND]     = loss;
        out[ND + 1] = expf(-sh[0]);
    }
}

// ---------------- launch ----------------
extern "C" void kernel_launch(void* const* d_in, const int* in_sizes, int n_in,
                              void* d_out, int out_size) {
    const float* z     = (const float*)d_in[0];   // [B,S,D] fp32
    const float* embed = (const float*)d_in[1];   // [K,D]  fp32
    float* out = (float*)d_out;
    (void)in_sizes; (void)n_in;

    int write_scalars = (out_size >= ND + 2) ? 1 : 0;
    int write_idx     = (out_size >= ND + 2 + N_ROWS) ? 1 : 0;

    zero_counts_kernel<<<(NCODES + 255) / 256, 256>>>();
    ee_kernel<<<NCODES / 8, 256>>>(embed);
    argmin_kernel<<<N_ROWS / BM, 256>>>(z, embed);
    gather_kernel<<<N_ROWS / 8, 256>>>(z, embed, out, write_idx);
    finalize_kernel<<<1, 256>>>(out, write_scalars);
}